// round 1
// baseline (speedup 1.0000x reference)
#include <cuda_runtime.h>
#include <math.h>

// ---------------- problem constants ----------------
#define S_LEN    4096
#define DMODEL   1024
#define N_HEADS  16
#define HEAD_DIM 64
#define QB       32          // queries per attention block
#define KB       160         // key window per block: QB + 2*64
#define HW       64          // half window
#define KSTRIDE  65          // padded K/V smem row stride (conflict-free)

// ---------------- scratch (no allocations allowed) ----------------
__device__ float g_Q[S_LEN * DMODEL];
__device__ float g_K[S_LEN * DMODEL];
__device__ float g_V[S_LEN * DMODEL];
__device__ float g_ctx[S_LEN * DMODEL];

// ---------------- GEMM: C[M,N] = A[M,K] @ B[N,K]^T + bias ----------------
#define BM 128
#define BN 128
#define BK 16

__global__ __launch_bounds__(256)
void gemm_nt_bias(const float* __restrict__ A, const float* __restrict__ B,
                  const float* __restrict__ bias, float* __restrict__ C,
                  int M, int N, int K)
{
    __shared__ float As[BK][BM + 4];
    __shared__ float Bs[BK][BN + 4];

    const int bm = blockIdx.y * BM;
    const int bn = blockIdx.x * BN;
    const int t  = threadIdx.x;
    const int tx = t & 15;         // 0..15
    const int ty = t >> 4;         // 0..15
    const int lr = t >> 2;         // 0..63 (load row)
    const int lc = (t & 3) * 4;    // 0,4,8,12 (load col within BK)

    float acc[2][2][4][4];
#pragma unroll
    for (int a = 0; a < 2; a++)
#pragma unroll
        for (int b = 0; b < 2; b++)
#pragma unroll
            for (int i = 0; i < 4; i++)
#pragma unroll
                for (int j = 0; j < 4; j++) acc[a][b][i][j] = 0.f;

    for (int k0 = 0; k0 < K; k0 += BK) {
#pragma unroll
        for (int h = 0; h < 2; h++) {
            int row = lr + h * 64;
            float4 av = *(const float4*)&A[(size_t)(bm + row) * K + k0 + lc];
            As[lc + 0][row] = av.x; As[lc + 1][row] = av.y;
            As[lc + 2][row] = av.z; As[lc + 3][row] = av.w;
            float4 bv = *(const float4*)&B[(size_t)(bn + row) * K + k0 + lc];
            Bs[lc + 0][row] = bv.x; Bs[lc + 1][row] = bv.y;
            Bs[lc + 2][row] = bv.z; Bs[lc + 3][row] = bv.w;
        }
        __syncthreads();

#pragma unroll
        for (int k = 0; k < BK; k++) {
            float ra[2][4], rb[2][4];
#pragma unroll
            for (int a = 0; a < 2; a++) {
                float4 va = *(const float4*)&As[k][a * 64 + ty * 4];
                ra[a][0] = va.x; ra[a][1] = va.y; ra[a][2] = va.z; ra[a][3] = va.w;
                float4 vb = *(const float4*)&Bs[k][a * 64 + tx * 4];
                rb[a][0] = vb.x; rb[a][1] = vb.y; rb[a][2] = vb.z; rb[a][3] = vb.w;
            }
#pragma unroll
            for (int a = 0; a < 2; a++)
#pragma unroll
                for (int i = 0; i < 4; i++)
#pragma unroll
                    for (int b = 0; b < 2; b++)
#pragma unroll
                        for (int j = 0; j < 4; j++)
                            acc[a][b][i][j] += ra[a][i] * rb[b][j];
        }
        __syncthreads();
    }

#pragma unroll
    for (int a = 0; a < 2; a++) {
#pragma unroll
        for (int i = 0; i < 4; i++) {
            int row = bm + a * 64 + ty * 4 + i;
#pragma unroll
            for (int b = 0; b < 2; b++) {
                int col = bn + b * 64 + tx * 4;
                float4 o;
                o.x = acc[a][b][i][0] + bias[col + 0];
                o.y = acc[a][b][i][1] + bias[col + 1];
                o.z = acc[a][b][i][2] + bias[col + 2];
                o.w = acc[a][b][i][3] + bias[col + 3];
                *(float4*)&C[(size_t)row * N + col] = o;
            }
        }
    }
}

// ---------------- sliding-window attention ----------------
// grid: (S/QB, H), 256 threads. Each warp owns 4 query rows.
__global__ __launch_bounds__(256)
void attn_kernel(const float* __restrict__ Q, const float* __restrict__ K,
                 const float* __restrict__ V, float* __restrict__ ctx)
{
    extern __shared__ float sm[];
    float* Qs = sm;                         // QB * HEAD_DIM
    float* Ks = Qs + QB * HEAD_DIM;         // KB * KSTRIDE
    float* Vs = Ks + KB * KSTRIDE;          // KB * KSTRIDE
    float* Ps = Vs + KB * KSTRIDE;          // QB * KB

    const int h    = blockIdx.y;
    const int q0   = blockIdx.x * QB;
    const int j0   = q0 - HW;
    const int t    = threadIdx.x;
    const int lane = t & 31;
    const int w    = t >> 5;                // warp 0..7
    const int col  = h * HEAD_DIM;

    // ---- load Q tile: 32x64 floats, float4 vectorized ----
    for (int i = t; i < QB * HEAD_DIM / 4; i += 256) {
        int r = i >> 4;
        int c = (i & 15) * 4;
        *(float4*)&Qs[r * HEAD_DIM + c] =
            *(const float4*)&Q[(size_t)(q0 + r) * DMODEL + col + c];
    }
    // ---- load K,V window: 160x64 each (zero-fill out of range) ----
    for (int i = t; i < KB * HEAD_DIM / 4; i += 256) {
        int r = i >> 4;
        int c = (i & 15) * 4;
        int j = j0 + r;
        float4 kv = make_float4(0.f, 0.f, 0.f, 0.f);
        float4 vv = make_float4(0.f, 0.f, 0.f, 0.f);
        if (j >= 0 && j < S_LEN) {
            kv = *(const float4*)&K[(size_t)j * DMODEL + col + c];
            vv = *(const float4*)&V[(size_t)j * DMODEL + col + c];
        }
        float* kd = &Ks[r * KSTRIDE + c];
        kd[0] = kv.x; kd[1] = kv.y; kd[2] = kv.z; kd[3] = kv.w;
        float* vd = &Vs[r * KSTRIDE + c];
        vd[0] = vv.x; vd[1] = vv.y; vd[2] = vv.z; vd[3] = vv.w;
    }
    __syncthreads();

    const int qb = w * 4;   // this warp's 4 query rows (local)

    // ---- scores: s[qi][jj] for key lk = lane + 32*jj ----
    float s[4][5];
#pragma unroll
    for (int qi = 0; qi < 4; qi++)
#pragma unroll
        for (int jj = 0; jj < 5; jj++) s[qi][jj] = 0.f;

    for (int d = 0; d < HEAD_DIM; d++) {
        float kvv[5];
#pragma unroll
        for (int jj = 0; jj < 5; jj++)
            kvv[jj] = Ks[(lane + 32 * jj) * KSTRIDE + d];
#pragma unroll
        for (int qi = 0; qi < 4; qi++) {
            float qv = Qs[(qb + qi) * HEAD_DIM + d];
#pragma unroll
            for (int jj = 0; jj < 5; jj++) s[qi][jj] += qv * kvv[jj];
        }
    }

    // ---- scale + mask + softmax (warp-local rows) ----
#pragma unroll
    for (int qi = 0; qi < 4; qi++) {
        const int ql = qb + qi;
        float m = -1e30f;
#pragma unroll
        for (int jj = 0; jj < 5; jj++) {
            int lk = lane + 32 * jj;
            int j  = j0 + lk;
            bool valid = (j >= 0) && (j < S_LEN) && (lk >= ql) && (lk <= ql + 128);
            s[qi][jj] = valid ? s[qi][jj] * 0.125f : -1e9f;
            m = fmaxf(m, s[qi][jj]);
        }
#pragma unroll
        for (int o = 16; o > 0; o >>= 1)
            m = fmaxf(m, __shfl_xor_sync(0xffffffffu, m, o));
        float sum = 0.f;
        float p[5];
#pragma unroll
        for (int jj = 0; jj < 5; jj++) {
            p[jj] = expf(s[qi][jj] - m);
            sum += p[jj];
        }
#pragma unroll
        for (int o = 16; o > 0; o >>= 1)
            sum += __shfl_xor_sync(0xffffffffu, sum, o);
        float inv = 1.0f / sum;
#pragma unroll
        for (int jj = 0; jj < 5; jj++)
            Ps[ql * KB + lane + 32 * jj] = p[jj] * inv;
    }
    __syncwarp();

    // ---- ctx: C[4][2] per lane, dims d = lane, lane+32 ----
    float acc[4][2];
#pragma unroll
    for (int qi = 0; qi < 4; qi++) { acc[qi][0] = 0.f; acc[qi][1] = 0.f; }

    for (int lk = 0; lk < KB; lk++) {
        float v0 = Vs[lk * KSTRIDE + lane];
        float v1 = Vs[lk * KSTRIDE + lane + 32];
#pragma unroll
        for (int qi = 0; qi < 4; qi++) {
            float pv = Ps[(qb + qi) * KB + lk];
            acc[qi][0] += pv * v0;
            acc[qi][1] += pv * v1;
        }
    }

#pragma unroll
    for (int qi = 0; qi < 4; qi++) {
        size_t base = (size_t)(q0 + qb + qi) * DMODEL + col;
        ctx[base + lane]      = acc[qi][0];
        ctx[base + lane + 32] = acc[qi][1];
    }
}

// ---------------- launch ----------------
extern "C" void kernel_launch(void* const* d_in, const int* in_sizes, int n_in,
                              void* d_out, int out_size)
{
    const float* x  = (const float*)d_in[0];
    const float* Wq = (const float*)d_in[1];
    const float* bq = (const float*)d_in[2];
    const float* Wk = (const float*)d_in[3];
    const float* bk = (const float*)d_in[4];
    const float* Wv = (const float*)d_in[5];
    const float* bv = (const float*)d_in[6];
    const float* Wo = (const float*)d_in[7];
    const float* bo = (const float*)d_in[8];
    float* out = (float*)d_out;

    float *Q, *K, *V, *CTX;
    cudaGetSymbolAddress((void**)&Q,   g_Q);
    cudaGetSymbolAddress((void**)&K,   g_K);
    cudaGetSymbolAddress((void**)&V,   g_V);
    cudaGetSymbolAddress((void**)&CTX, g_ctx);

    const int smem_attn = (QB * HEAD_DIM + 2 * KB * KSTRIDE + QB * KB) * (int)sizeof(float);
    cudaFuncSetAttribute(attn_kernel, cudaFuncAttributeMaxDynamicSharedMemorySize, smem_attn);

    dim3 gg(DMODEL / BN, S_LEN / BM);   // (8, 32)
    gemm_nt_bias<<<gg, 256>>>(x, Wq, bq, Q, S_LEN, DMODEL, DMODEL);
    gemm_nt_bias<<<gg, 256>>>(x, Wk, bk, K, S_LEN, DMODEL, DMODEL);
    gemm_nt_bias<<<gg, 256>>>(x, Wv, bv, V, S_LEN, DMODEL, DMODEL);

    dim3 ga(S_LEN / QB, N_HEADS);       // (128, 16)
    attn_kernel<<<ga, 256, smem_attn>>>(Q, K, V, CTX);

    gemm_nt_bias<<<gg, 256>>>(CTX, Wo, bo, out, S_LEN, DMODEL, DMODEL);
}

// round 3
// speedup vs baseline: 2.0402x; 2.0402x over previous
#include <cuda_runtime.h>
#include <cuda_bf16.h>
#include <math.h>

// ---------------- problem constants ----------------
#define S_LEN    4096
#define DMODEL   1024
#define N_HEADS  16
#define HEAD_DIM 64
#define QB       32
#define KB       160
#define HW       64
#define KSTRIDE  65

// ---------------- scratch (no allocations allowed) ----------------
__device__ float g_Q[S_LEN * DMODEL];
__device__ float g_K[S_LEN * DMODEL];
__device__ float g_V[S_LEN * DMODEL];
__device__ float g_ctx[S_LEN * DMODEL];

__device__ __nv_bfloat16 g_xh[S_LEN * DMODEL];
__device__ __nv_bfloat16 g_xl[S_LEN * DMODEL];
__device__ __nv_bfloat16 g_ch[S_LEN * DMODEL];
__device__ __nv_bfloat16 g_cl[S_LEN * DMODEL];
__device__ __nv_bfloat16 g_Wqh[DMODEL * DMODEL];
__device__ __nv_bfloat16 g_Wql[DMODEL * DMODEL];
__device__ __nv_bfloat16 g_Wkh[DMODEL * DMODEL];
__device__ __nv_bfloat16 g_Wkl[DMODEL * DMODEL];
__device__ __nv_bfloat16 g_Wvh[DMODEL * DMODEL];
__device__ __nv_bfloat16 g_Wvl[DMODEL * DMODEL];
__device__ __nv_bfloat16 g_Woh[DMODEL * DMODEL];
__device__ __nv_bfloat16 g_Wol[DMODEL * DMODEL];

// ---------------- small helpers ----------------
__device__ __forceinline__ unsigned smem_u32(const void* p) {
    unsigned a;
    asm("{ .reg .u64 t; cvta.to.shared.u64 t, %1; cvt.u32.u64 %0, t; }" : "=r"(a) : "l"(p));
    return a;
}
__device__ __forceinline__ void cp16(unsigned dst, const void* src) {
    asm volatile("cp.async.cg.shared.global [%0], [%1], 16;" :: "r"(dst), "l"(src));
}
__device__ __forceinline__ void ldm_x4(unsigned* r, unsigned addr) {
    asm volatile("ldmatrix.sync.aligned.m8n8.x4.shared.b16 {%0,%1,%2,%3}, [%4];"
                 : "=r"(r[0]), "=r"(r[1]), "=r"(r[2]), "=r"(r[3]) : "r"(addr));
}
__device__ __forceinline__ void mma16816(float* d, const unsigned* a, const unsigned* b) {
    asm volatile(
        "mma.sync.aligned.m16n8k16.row.col.f32.bf16.bf16.f32 "
        "{%0,%1,%2,%3}, {%4,%5,%6,%7}, {%8,%9}, {%0,%1,%2,%3};"
        : "+f"(d[0]), "+f"(d[1]), "+f"(d[2]), "+f"(d[3])
        : "r"(a[0]), "r"(a[1]), "r"(a[2]), "r"(a[3]), "r"(b[0]), "r"(b[1]));
}

// ---------------- split: fp32 -> bf16 hi + bf16 lo ----------------
__global__ __launch_bounds__(256)
void split_bf16(const float* __restrict__ in, __nv_bfloat16* __restrict__ hi,
                __nv_bfloat16* __restrict__ lo)
{
    int i = (blockIdx.x * 256 + threadIdx.x) * 4;
    float4 a = *(const float4*)(in + i);
    __nv_bfloat16 h0 = __float2bfloat16(a.x);
    __nv_bfloat16 h1 = __float2bfloat16(a.y);
    __nv_bfloat16 h2 = __float2bfloat16(a.z);
    __nv_bfloat16 h3 = __float2bfloat16(a.w);
    __nv_bfloat16 l0 = __float2bfloat16(a.x - __bfloat162float(h0));
    __nv_bfloat16 l1 = __float2bfloat16(a.y - __bfloat162float(h1));
    __nv_bfloat16 l2 = __float2bfloat16(a.z - __bfloat162float(h2));
    __nv_bfloat16 l3 = __float2bfloat16(a.w - __bfloat162float(h3));
    __nv_bfloat162 hv0(h0, h1), hv1(h2, h3), lv0(l0, l1), lv1(l2, l3);
    uint2 hp, lp;
    hp.x = *(unsigned*)&hv0; hp.y = *(unsigned*)&hv1;
    lp.x = *(unsigned*)&lv0; lp.y = *(unsigned*)&lv1;
    *(uint2*)(hi + i) = hp;
    *(uint2*)(lo + i) = lp;
}

// ---------------- mma.sync bf16x3 GEMM ----------------
// C[4096,1024] = A @ B^T + bias, A,B pre-split into bf16 hi/lo.
// 128x128 tile, BK=32, 8 warps (2x4), warp tile 64x32, double-buffered cp.async.
#define ROWB  80                      // 64B data + 16B pad (conflict-free ldmatrix)
#define PLANE (128 * ROWB)            // 10240 B
#define STAGE (4 * PLANE)             // 40960 B
#define GSMEM (2 * STAGE)             // 81920 B
#define NCHUNK 32                     // 1024 / 32

__global__ __launch_bounds__(256)
void gemm_mma_bf16x3(const __nv_bfloat16* __restrict__ Ah, const __nv_bfloat16* __restrict__ Al,
                     const __nv_bfloat16* __restrict__ Bh, const __nv_bfloat16* __restrict__ Bl,
                     const float* __restrict__ bias, float* __restrict__ C)
{
    extern __shared__ char smem[];
    const int t = threadIdx.x, lane = t & 31, wid = t >> 5;
    const int wm = wid >> 2, wn = wid & 3;          // warp grid 2 x 4
    const int bm = blockIdx.y * 128, bn = blockIdx.x * 128;

    float acc[4][4][4];
#pragma unroll
    for (int mt = 0; mt < 4; mt++)
#pragma unroll
        for (int nt = 0; nt < 4; nt++)
#pragma unroll
            for (int r = 0; r < 4; r++) acc[mt][nt][r] = 0.f;

    // per-thread copy coordinates: 512 (row,seg) pairs per plane, 2 iters
    const int r0 = t >> 2, s0 = t & 3;              // iter 0: rows 0..63
    const int r1 = r0 + 64;                          // iter 1: rows 64..127

    const __nv_bfloat16* srcs[4] = {Ah, Al, Bh, Bl};
    const int rowbase[4] = {bm, bm, bn, bn};

#define ISSUE(cc, bb)                                                            \
    {                                                                            \
        char* sb = smem + (bb) * STAGE;                                          \
        const int gk = (cc) * 32 + s0 * 8;                                       \
        _Pragma("unroll")                                                        \
        for (int pl = 0; pl < 4; pl++) {                                         \
            const __nv_bfloat16* gp = srcs[pl] + (size_t)rowbase[pl] * DMODEL + gk; \
            unsigned db = smem_u32(sb + pl * PLANE + s0 * 16);                   \
            cp16(db + r0 * ROWB, gp + (size_t)r0 * DMODEL);                      \
            cp16(db + r1 * ROWB, gp + (size_t)r1 * DMODEL);                      \
        }                                                                        \
        asm volatile("cp.async.commit_group;" ::: "memory");                     \
    }

    ISSUE(0, 0);

    // ldmatrix lane addressing
    const int a_row = wm * 64 + (lane & 15);
    const unsigned a_coff = (lane >> 4) * 16;
    const int b_row = wn * 32 + (lane & 7) + ((lane >> 4) << 3);
    const unsigned b_coff = ((lane >> 3) & 1) * 16;

    for (int c = 0; c < NCHUNK; c++) {
        if (c + 1 < NCHUNK) {
            ISSUE(c + 1, (c + 1) & 1);
            asm volatile("cp.async.wait_group 1;" ::: "memory");
        } else {
            asm volatile("cp.async.wait_group 0;" ::: "memory");
        }
        __syncthreads();

        char* sb = smem + (c & 1) * STAGE;
        const unsigned sAh = smem_u32(sb);
        const unsigned sAl = sAh + PLANE;
        const unsigned sBh = sAh + 2 * PLANE;
        const unsigned sBl = sAh + 3 * PLANE;

#pragma unroll
        for (int ks = 0; ks < 2; ks++) {
            const unsigned ka = ks * 32;
            unsigned ah[4][4], al[4][4];
#pragma unroll
            for (int mt = 0; mt < 4; mt++) {
                unsigned off = (unsigned)((a_row + mt * 16) * ROWB) + ka + a_coff;
                ldm_x4(ah[mt], sAh + off);
                ldm_x4(al[mt], sAl + off);
            }
#pragma unroll
            for (int pr = 0; pr < 2; pr++) {
                unsigned bh[4], bl[4];
                unsigned off = (unsigned)((b_row + pr * 16) * ROWB) + ka + b_coff;
                ldm_x4(bh, sBh + off);
                ldm_x4(bl, sBl + off);
#pragma unroll
                for (int half = 0; half < 2; half++) {
                    const int nt = pr * 2 + half;
#pragma unroll
                    for (int mt = 0; mt < 4; mt++) {
                        mma16816(acc[mt][nt], ah[mt], &bh[half * 2]);
                        mma16816(acc[mt][nt], ah[mt], &bl[half * 2]);
                        mma16816(acc[mt][nt], al[mt], &bh[half * 2]);
                    }
                }
            }
        }
        __syncthreads();
    }

    // ---- epilogue: acc -> C with bias ----
    const int er = lane >> 2, ec = (lane & 3) * 2;
#pragma unroll
    for (int mt = 0; mt < 4; mt++) {
        const int row = bm + wm * 64 + mt * 16 + er;
#pragma unroll
        for (int nt = 0; nt < 4; nt++) {
            const int col = bn + wn * 32 + nt * 8 + ec;
            const float b0 = bias[col], b1 = bias[col + 1];
            float2 o0 = make_float2(acc[mt][nt][0] + b0, acc[mt][nt][1] + b1);
            float2 o1 = make_float2(acc[mt][nt][2] + b0, acc[mt][nt][3] + b1);
            *(float2*)&C[(size_t)row * DMODEL + col] = o0;
            *(float2*)&C[(size_t)(row + 8) * DMODEL + col] = o1;
        }
    }
#undef ISSUE
}

// ---------------- sliding-window attention (unchanged from R1) ----------------
__global__ __launch_bounds__(256)
void attn_kernel(const float* __restrict__ Q, const float* __restrict__ K,
                 const float* __restrict__ V, float* __restrict__ ctx)
{
    extern __shared__ float sm[];
    float* Qs = sm;
    float* Ks = Qs + QB * HEAD_DIM;
    float* Vs = Ks + KB * KSTRIDE;
    float* Ps = Vs + KB * KSTRIDE;

    const int h    = blockIdx.y;
    const int q0   = blockIdx.x * QB;
    const int j0   = q0 - HW;
    const int t    = threadIdx.x;
    const int lane = t & 31;
    const int w    = t >> 5;
    const int col  = h * HEAD_DIM;

    for (int i = t; i < QB * HEAD_DIM / 4; i += 256) {
        int r = i >> 4;
        int c = (i & 15) * 4;
        *(float4*)&Qs[r * HEAD_DIM + c] =
            *(const float4*)&Q[(size_t)(q0 + r) * DMODEL + col + c];
    }
    for (int i = t; i < KB * HEAD_DIM / 4; i += 256) {
        int r = i >> 4;
        int c = (i & 15) * 4;
        int j = j0 + r;
        float4 kv = make_float4(0.f, 0.f, 0.f, 0.f);
        float4 vv = make_float4(0.f, 0.f, 0.f, 0.f);
        if (j >= 0 && j < S_LEN) {
            kv = *(const float4*)&K[(size_t)j * DMODEL + col + c];
            vv = *(const float4*)&V[(size_t)j * DMODEL + col + c];
        }
        float* kd = &Ks[r * KSTRIDE + c];
        kd[0] = kv.x; kd[1] = kv.y; kd[2] = kv.z; kd[3] = kv.w;
        float* vd = &Vs[r * KSTRIDE + c];
        vd[0] = vv.x; vd[1] = vv.y; vd[2] = vv.z; vd[3] = vv.w;
    }
    __syncthreads();

    const int qb = w * 4;

    float s[4][5];
#pragma unroll
    for (int qi = 0; qi < 4; qi++)
#pragma unroll
        for (int jj = 0; jj < 5; jj++) s[qi][jj] = 0.f;

    for (int d = 0; d < HEAD_DIM; d++) {
        float kvv[5];
#pragma unroll
        for (int jj = 0; jj < 5; jj++)
            kvv[jj] = Ks[(lane + 32 * jj) * KSTRIDE + d];
#pragma unroll
        for (int qi = 0; qi < 4; qi++) {
            float qv = Qs[(qb + qi) * HEAD_DIM + d];
#pragma unroll
            for (int jj = 0; jj < 5; jj++) s[qi][jj] += qv * kvv[jj];
        }
    }

#pragma unroll
    for (int qi = 0; qi < 4; qi++) {
        const int ql = qb + qi;
        float m = -1e30f;
#pragma unroll
        for (int jj = 0; jj < 5; jj++) {
            int lk = lane + 32 * jj;
            int j  = j0 + lk;
            bool valid = (j >= 0) && (j < S_LEN) && (lk >= ql) && (lk <= ql + 128);
            s[qi][jj] = valid ? s[qi][jj] * 0.125f : -1e9f;
            m = fmaxf(m, s[qi][jj]);
        }
#pragma unroll
        for (int o = 16; o > 0; o >>= 1)
            m = fmaxf(m, __shfl_xor_sync(0xffffffffu, m, o));
        float sum = 0.f;
        float p[5];
#pragma unroll
        for (int jj = 0; jj < 5; jj++) {
            p[jj] = expf(s[qi][jj] - m);
            sum += p[jj];
        }
#pragma unroll
        for (int o = 16; o > 0; o >>= 1)
            sum += __shfl_xor_sync(0xffffffffu, sum, o);
        float inv = 1.0f / sum;
#pragma unroll
        for (int jj = 0; jj < 5; jj++)
            Ps[ql * KB + lane + 32 * jj] = p[jj] * inv;
    }
    __syncwarp();

    float acc[4][2];
#pragma unroll
    for (int qi = 0; qi < 4; qi++) { acc[qi][0] = 0.f; acc[qi][1] = 0.f; }

    for (int lk = 0; lk < KB; lk++) {
        float v0 = Vs[lk * KSTRIDE + lane];
        float v1 = Vs[lk * KSTRIDE + lane + 32];
#pragma unroll
        for (int qi = 0; qi < 4; qi++) {
            float pv = Ps[(qb + qi) * KB + lk];
            acc[qi][0] += pv * v0;
            acc[qi][1] += pv * v1;
        }
    }

#pragma unroll
    for (int qi = 0; qi < 4; qi++) {
        size_t base = (size_t)(q0 + qb + qi) * DMODEL + col;
        ctx[base + lane]      = acc[qi][0];
        ctx[base + lane + 32] = acc[qi][1];
    }
}

// ---------------- launch ----------------
extern "C" void kernel_launch(void* const* d_in, const int* in_sizes, int n_in,
                              void* d_out, int out_size)
{
    const float* x  = (const float*)d_in[0];
    const float* Wq = (const float*)d_in[1];
    const float* bq = (const float*)d_in[2];
    const float* Wk = (const float*)d_in[3];
    const float* bk = (const float*)d_in[4];
    const float* Wv = (const float*)d_in[5];
    const float* bv = (const float*)d_in[6];
    const float* Wo = (const float*)d_in[7];
    const float* bo = (const float*)d_in[8];
    float* out = (float*)d_out;

    float *Q, *K, *V, *CTX;
    cudaGetSymbolAddress((void**)&Q,   g_Q);
    cudaGetSymbolAddress((void**)&K,   g_K);
    cudaGetSymbolAddress((void**)&V,   g_V);
    cudaGetSymbolAddress((void**)&CTX, g_ctx);
    __nv_bfloat16 *xh, *xl, *ch, *cl;
    __nv_bfloat16 *wqh, *wql, *wkh, *wkl, *wvh, *wvl, *woh, *wol;
    cudaGetSymbolAddress((void**)&xh, g_xh);   cudaGetSymbolAddress((void**)&xl, g_xl);
    cudaGetSymbolAddress((void**)&ch, g_ch);   cudaGetSymbolAddress((void**)&cl, g_cl);
    cudaGetSymbolAddress((void**)&wqh, g_Wqh); cudaGetSymbolAddress((void**)&wql, g_Wql);
    cudaGetSymbolAddress((void**)&wkh, g_Wkh); cudaGetSymbolAddress((void**)&wkl, g_Wkl);
    cudaGetSymbolAddress((void**)&wvh, g_Wvh); cudaGetSymbolAddress((void**)&wvl, g_Wvl);
    cudaGetSymbolAddress((void**)&woh, g_Woh); cudaGetSymbolAddress((void**)&wol, g_Wol);

    const int smem_attn = (QB * HEAD_DIM + 2 * KB * KSTRIDE + QB * KB) * (int)sizeof(float);
    cudaFuncSetAttribute(attn_kernel, cudaFuncAttributeMaxDynamicSharedMemorySize, smem_attn);
    cudaFuncSetAttribute(gemm_mma_bf16x3, cudaFuncAttributeMaxDynamicSharedMemorySize, GSMEM);

    const int nx = S_LEN * DMODEL;     // 4M
    const int nw = DMODEL * DMODEL;    // 1M

    split_bf16<<<nx / 1024, 256>>>(x,  xh,  xl);
    split_bf16<<<nw / 1024, 256>>>(Wq, wqh, wql);
    split_bf16<<<nw / 1024, 256>>>(Wk, wkh, wkl);
    split_bf16<<<nw / 1024, 256>>>(Wv, wvh, wvl);
    split_bf16<<<nw / 1024, 256>>>(Wo, woh, wol);

    dim3 gg(DMODEL / 128, S_LEN / 128);   // (8, 32)
    gemm_mma_bf16x3<<<gg, 256, GSMEM>>>(xh, xl, wqh, wql, bq, Q);
    gemm_mma_bf16x3<<<gg, 256, GSMEM>>>(xh, xl, wkh, wkl, bk, K);
    gemm_mma_bf16x3<<<gg, 256, GSMEM>>>(xh, xl, wvh, wvl, bv, V);

    dim3 ga(S_LEN / QB, N_HEADS);         // (128, 16)
    attn_kernel<<<ga, 256, smem_attn>>>(Q, K, V, CTX);

    split_bf16<<<nx / 1024, 256>>>(CTX, ch, cl);
    gemm_mma_bf16x3<<<gg, 256, GSMEM>>>(ch, cl, woh, wol, bo, out);
}

// round 5
// speedup vs baseline: 2.0705x; 1.0148x over previous
#include <cuda_runtime.h>
#include <cuda_bf16.h>
#include <math.h>

// ---------------- problem constants ----------------
#define S_LEN    4096
#define DMODEL   1024
#define N_HEADS  16
#define HEAD_DIM 64

// ---------------- scratch (no allocations allowed) ----------------
__device__ __nv_bfloat16 g_xh[S_LEN * DMODEL];
__device__ __nv_bfloat16 g_xl[S_LEN * DMODEL];
__device__ __nv_bfloat16 g_qh[S_LEN * DMODEL];
__device__ __nv_bfloat16 g_ql[S_LEN * DMODEL];
__device__ __nv_bfloat16 g_kh[S_LEN * DMODEL];
__device__ __nv_bfloat16 g_kl[S_LEN * DMODEL];
__device__ __nv_bfloat16 g_vh[S_LEN * DMODEL];
__device__ __nv_bfloat16 g_vl[S_LEN * DMODEL];
__device__ __nv_bfloat16 g_ch[S_LEN * DMODEL];
__device__ __nv_bfloat16 g_cl[S_LEN * DMODEL];
__device__ __nv_bfloat16 g_Wqh[DMODEL * DMODEL];
__device__ __nv_bfloat16 g_Wql[DMODEL * DMODEL];
__device__ __nv_bfloat16 g_Wkh[DMODEL * DMODEL];
__device__ __nv_bfloat16 g_Wkl[DMODEL * DMODEL];
__device__ __nv_bfloat16 g_Wvh[DMODEL * DMODEL];
__device__ __nv_bfloat16 g_Wvl[DMODEL * DMODEL];
__device__ __nv_bfloat16 g_Woh[DMODEL * DMODEL];
__device__ __nv_bfloat16 g_Wol[DMODEL * DMODEL];

// ---------------- small helpers ----------------
__device__ __forceinline__ unsigned smem_u32(const void* p) {
    unsigned a;
    asm("{ .reg .u64 t; cvta.to.shared.u64 t, %1; cvt.u32.u64 %0, t; }" : "=r"(a) : "l"(p));
    return a;
}
__device__ __forceinline__ void cp16(unsigned dst, const void* src) {
    asm volatile("cp.async.cg.shared.global [%0], [%1], 16;" :: "r"(dst), "l"(src));
}
__device__ __forceinline__ void ldm_x4(unsigned* r, unsigned addr) {
    asm volatile("ldmatrix.sync.aligned.m8n8.x4.shared.b16 {%0,%1,%2,%3}, [%4];"
                 : "=r"(r[0]), "=r"(r[1]), "=r"(r[2]), "=r"(r[3]) : "r"(addr));
}
__device__ __forceinline__ void ldm_x4t(unsigned* r, unsigned addr) {
    asm volatile("ldmatrix.sync.aligned.m8n8.x4.trans.shared.b16 {%0,%1,%2,%3}, [%4];"
                 : "=r"(r[0]), "=r"(r[1]), "=r"(r[2]), "=r"(r[3]) : "r"(addr));
}
__device__ __forceinline__ void mma16816(float* d, const unsigned* a, const unsigned* b) {
    asm volatile(
        "mma.sync.aligned.m16n8k16.row.col.f32.bf16.bf16.f32 "
        "{%0,%1,%2,%3}, {%4,%5,%6,%7}, {%8,%9}, {%0,%1,%2,%3};"
        : "+f"(d[0]), "+f"(d[1]), "+f"(d[2]), "+f"(d[3])
        : "r"(a[0]), "r"(a[1]), "r"(a[2]), "r"(a[3]), "r"(b[0]), "r"(b[1]));
}
__device__ __forceinline__ unsigned packbf(float lo, float hi) {
    unsigned r;
    asm("cvt.rn.bf16x2.f32 %0, %1, %2;" : "=r"(r) : "f"(hi), "f"(lo));
    return r;
}
__device__ __forceinline__ float bflo_f(unsigned u) { return __uint_as_float(u << 16); }
__device__ __forceinline__ float bfhi_f(unsigned u) { return __uint_as_float(u & 0xffff0000u); }
__device__ __forceinline__ float ex2(float x) {
    float y; asm("ex2.approx.ftz.f32 %0, %1;" : "=f"(y) : "f"(x)); return y;
}
__device__ __forceinline__ float rcp(float x) {
    float y; asm("rcp.approx.ftz.f32 %0, %1;" : "=f"(y) : "f"(x)); return y;
}

// ---------------- split: fp32 -> bf16 hi + bf16 lo ----------------
__global__ __launch_bounds__(256)
void split_bf16(const float* __restrict__ in, __nv_bfloat16* __restrict__ hi,
                __nv_bfloat16* __restrict__ lo)
{
    int i = (blockIdx.x * 256 + threadIdx.x) * 4;
    float4 a = *(const float4*)(in + i);
    unsigned h0 = packbf(a.x, a.y), h1 = packbf(a.z, a.w);
    unsigned l0 = packbf(a.x - bflo_f(h0), a.y - bfhi_f(h0));
    unsigned l1 = packbf(a.z - bflo_f(h1), a.w - bfhi_f(h1));
    uint2 hp = make_uint2(h0, h1), lp = make_uint2(l0, l1);
    *(uint2*)((__nv_bfloat16*)hi + i) = hp;
    *(uint2*)((__nv_bfloat16*)lo + i) = lp;
}

// ---------------- shared GEMM body (mma.sync bf16x3) ----------------
// 128x128 tile, BK=32, 8 warps (2x4), warp tile 64x32, 4-stage cp.async.
#define ROWB   80
#define PLANE  (128 * ROWB)
#define STAGE  (4 * PLANE)
#define NSTAGE 4
#define GSMEM  (NSTAGE * STAGE)
#define NCHUNK 32

// mode 0: C = fp32 out+bias ; mode 1: write bf16 hi/lo pair arrays
__device__ __forceinline__
void gemm_body(char* smem,
               const __nv_bfloat16* __restrict__ Ah, const __nv_bfloat16* __restrict__ Al,
               const __nv_bfloat16* __restrict__ Bh, const __nv_bfloat16* __restrict__ Bl,
               const float* __restrict__ bias, int bm, int bn,
               int mode, float* __restrict__ C,
               __nv_bfloat16* __restrict__ Ch, __nv_bfloat16* __restrict__ Cl)
{
    const int t = threadIdx.x, lane = t & 31, wid = t >> 5;
    const int wm = wid >> 2, wn = wid & 3;

    float acc[4][4][4];
#pragma unroll
    for (int mt = 0; mt < 4; mt++)
#pragma unroll
        for (int nt = 0; nt < 4; nt++)
#pragma unroll
            for (int r = 0; r < 4; r++) acc[mt][nt][r] = 0.f;

    const int r0 = t >> 2, s0 = t & 3;
    const int r1 = r0 + 64;

    const __nv_bfloat16* srcs[4] = {Ah, Al, Bh, Bl};
    const int rowbase[4] = {bm, bm, bn, bn};

#define ISSUE(cc)                                                                 \
    {                                                                             \
        char* sb = smem + ((cc) & (NSTAGE - 1)) * STAGE;                          \
        const int gk = (cc) * 32 + s0 * 8;                                        \
        _Pragma("unroll")                                                         \
        for (int pl = 0; pl < 4; pl++) {                                          \
            const __nv_bfloat16* gp = srcs[pl] + (size_t)rowbase[pl] * DMODEL + gk; \
            unsigned db = smem_u32(sb + pl * PLANE + s0 * 16);                    \
            cp16(db + r0 * ROWB, gp + (size_t)r0 * DMODEL);                       \
            cp16(db + r1 * ROWB, gp + (size_t)r1 * DMODEL);                       \
        }                                                                         \
        asm volatile("cp.async.commit_group;" ::: "memory");                      \
    }

    ISSUE(0); ISSUE(1); ISSUE(2);

    const int a_row = wm * 64 + (lane & 15);
    const unsigned a_coff = (lane >> 4) * 16;
    const int b_row = wn * 32 + (lane & 7) + ((lane >> 4) << 3);
    const unsigned b_coff = ((lane >> 3) & 1) * 16;

    for (int c = 0; c < NCHUNK; c++) {
        if (c + 3 < NCHUNK) {
            ISSUE(c + 3);
            asm volatile("cp.async.wait_group 3;" ::: "memory");
        } else if (c + 2 < NCHUNK) {
            asm volatile("cp.async.wait_group 2;" ::: "memory");
        } else if (c + 1 < NCHUNK) {
            asm volatile("cp.async.wait_group 1;" ::: "memory");
        } else {
            asm volatile("cp.async.wait_group 0;" ::: "memory");
        }
        __syncthreads();

        char* sb = smem + (c & (NSTAGE - 1)) * STAGE;
        const unsigned sAh = smem_u32(sb);
        const unsigned sAl = sAh + PLANE;
        const unsigned sBh = sAh + 2 * PLANE;
        const unsigned sBl = sAh + 3 * PLANE;

#pragma unroll
        for (int ks = 0; ks < 2; ks++) {
            const unsigned ka = ks * 32;
            unsigned ah[4][4], al[4][4];
#pragma unroll
            for (int mt = 0; mt < 4; mt++) {
                unsigned off = (unsigned)((a_row + mt * 16) * ROWB) + ka + a_coff;
                ldm_x4(ah[mt], sAh + off);
                ldm_x4(al[mt], sAl + off);
            }
#pragma unroll
            for (int pr = 0; pr < 2; pr++) {
                unsigned bh[4], bl[4];
                unsigned off = (unsigned)((b_row + pr * 16) * ROWB) + ka + b_coff;
                ldm_x4(bh, sBh + off);
                ldm_x4(bl, sBl + off);
#pragma unroll
                for (int half = 0; half < 2; half++) {
                    const int nt = pr * 2 + half;
#pragma unroll
                    for (int mt = 0; mt < 4; mt++) {
                        mma16816(acc[mt][nt], ah[mt], &bh[half * 2]);
                        mma16816(acc[mt][nt], ah[mt], &bl[half * 2]);
                        mma16816(acc[mt][nt], al[mt], &bh[half * 2]);
                    }
                }
            }
        }
        __syncthreads();
    }
#undef ISSUE

    // ---- epilogue ----
    const int er = lane >> 2, ec = (lane & 3) * 2;
#pragma unroll
    for (int mt = 0; mt < 4; mt++) {
        const int row = bm + wm * 64 + mt * 16 + er;
#pragma unroll
        for (int nt = 0; nt < 4; nt++) {
            const int col = bn + wn * 32 + nt * 8 + ec;
            const float b0 = bias[col], b1 = bias[col + 1];
            float v0 = acc[mt][nt][0] + b0, v1 = acc[mt][nt][1] + b1;
            float v2 = acc[mt][nt][2] + b0, v3 = acc[mt][nt][3] + b1;
            if (mode == 0) {
                *(float2*)&C[(size_t)row * DMODEL + col] = make_float2(v0, v1);
                *(float2*)&C[(size_t)(row + 8) * DMODEL + col] = make_float2(v2, v3);
            } else {
                unsigned hp0 = packbf(v0, v1);
                unsigned lp0 = packbf(v0 - bflo_f(hp0), v1 - bfhi_f(hp0));
                unsigned hp1 = packbf(v2, v3);
                unsigned lp1 = packbf(v2 - bflo_f(hp1), v3 - bfhi_f(hp1));
                *(unsigned*)&Ch[(size_t)row * DMODEL + col] = hp0;
                *(unsigned*)&Cl[(size_t)row * DMODEL + col] = lp0;
                *(unsigned*)&Ch[(size_t)(row + 8) * DMODEL + col] = hp1;
                *(unsigned*)&Cl[(size_t)(row + 8) * DMODEL + col] = lp1;
            }
        }
    }
}

// ---- fused QKV projection: grid (24, 32); blockIdx.x/8 selects Q/K/V ----
__global__ __launch_bounds__(256)
void gemm_qkv(const float* __restrict__ bq, const float* __restrict__ bk,
              const float* __restrict__ bv)
{
    extern __shared__ char smem[];
    const int which = blockIdx.x >> 3;
    const int bn = (blockIdx.x & 7) * 128;
    const int bm = blockIdx.y * 128;
    const __nv_bfloat16* Bh = (which == 0) ? g_Wqh : (which == 1) ? g_Wkh : g_Wvh;
    const __nv_bfloat16* Bl = (which == 0) ? g_Wql : (which == 1) ? g_Wkl : g_Wvl;
    const float* bias = (which == 0) ? bq : (which == 1) ? bk : bv;
    __nv_bfloat16* Ch = (which == 0) ? g_qh : (which == 1) ? g_kh : g_vh;
    __nv_bfloat16* Cl = (which == 0) ? g_ql : (which == 1) ? g_kl : g_vl;
    gemm_body(smem, g_xh, g_xl, Bh, Bl, bias, bm, bn, 1, nullptr, Ch, Cl);
}

// ---- output projection: ctx(hi/lo) @ Wo^T + bo -> fp32 out ----
__global__ __launch_bounds__(256)
void gemm_out(const float* __restrict__ bo, float* __restrict__ out)
{
    extern __shared__ char smem[];
    gemm_body(smem, g_ch, g_cl, g_Woh, g_Wol, bo,
              blockIdx.y * 128, blockIdx.x * 128, 0, out, nullptr, nullptr);
}

// ---------------- tensorized sliding-window attention ----------------
// grid (S/64, H), 128 threads (4 warps). Each warp: 16 query rows x 192 keys.
// Row stride AROWB = 128B data + 16B pad -> conflict-free ldmatrix (r*9 mod 8 perm).
#define AT_Q   64
#define AT_K   192
#define AROWB  144
#define A_SQH  0
#define A_SQL  (64 * AROWB)                 // 9216
#define A_SKH  (2 * 64 * AROWB)             // 18432
#define A_SKL  (A_SKH + AT_K * AROWB)       // 46080
#define A_SVH  (A_SKL + AT_K * AROWB)       // 73728
#define A_SVL  (A_SVH + AT_K * AROWB)       // 101376
#define A_SMEM (A_SVL + AT_K * AROWB)       // 129024

__global__ __launch_bounds__(128)
void attn_mma()
{
    extern __shared__ char smem[];
    const unsigned sb = smem_u32(smem);
    const int t = threadIdx.x, lane = t & 31, w = t >> 5;
    const int h = blockIdx.y;
    const int q0 = blockIdx.x * AT_Q;
    const int j0 = q0 - 64;
    const int col = h * HEAD_DIM;

    // ---- load Q (64x64) hi/lo ----
#pragma unroll
    for (int i = 0; i < 4; i++) {
        int idx = t + i * 128;               // 0..511
        int r = idx >> 3, sg = idx & 7;
        size_t go = (size_t)(q0 + r) * DMODEL + col + sg * 8;
        *(uint4*)(smem + A_SQH + r * AROWB + sg * 16) = *(const uint4*)(g_qh + go);
        *(uint4*)(smem + A_SQL + r * AROWB + sg * 16) = *(const uint4*)(g_ql + go);
    }
    // ---- load K,V window (192x64) hi/lo, zero-fill out of range ----
#pragma unroll
    for (int i = 0; i < 12; i++) {
        int idx = t + i * 128;               // 0..1535
        int r = idx >> 3, sg = idx & 7;
        int j = j0 + r;
        uint4 kh = make_uint4(0,0,0,0), kl = kh, vh = kh, vl = kh;
        if ((unsigned)j < (unsigned)S_LEN) {
            size_t go = (size_t)j * DMODEL + col + sg * 8;
            kh = *(const uint4*)(g_kh + go);
            kl = *(const uint4*)(g_kl + go);
            vh = *(const uint4*)(g_vh + go);
            vl = *(const uint4*)(g_vl + go);
        }
        unsigned so = r * AROWB + sg * 16;
        *(uint4*)(smem + A_SKH + so) = kh;
        *(uint4*)(smem + A_SKL + so) = kl;
        *(uint4*)(smem + A_SVH + so) = vh;
        *(uint4*)(smem + A_SVL + so) = vl;
    }
    __syncthreads();

    // ---- S = Q K^T  (bf16x3), 16 rows x 192 cols per warp ----
    float sc[24][4];
#pragma unroll
    for (int nt = 0; nt < 24; nt++)
#pragma unroll
        for (int r = 0; r < 4; r++) sc[nt][r] = 0.f;

    const unsigned a_base = (unsigned)((w * 16 + (lane & 15)) * AROWB) + ((lane >> 4) << 4);
    const int b_lrow = (lane & 7) + ((lane >> 4) << 3);
    const unsigned b_coff = ((lane >> 3) & 1) << 4;

#pragma unroll
    for (int kc = 0; kc < 4; kc++) {
        unsigned ah[4], al[4];
        ldm_x4(ah, sb + A_SQH + a_base + kc * 32);
        ldm_x4(al, sb + A_SQL + a_base + kc * 32);
#pragma unroll
        for (int pr = 0; pr < 12; pr++) {
            unsigned bh[4], bl[4];
            unsigned off = (unsigned)((pr * 16 + b_lrow) * AROWB) + kc * 32 + b_coff;
            ldm_x4(bh, sb + A_SKH + off);
            ldm_x4(bl, sb + A_SKL + off);
#pragma unroll
            for (int half = 0; half < 2; half++) {
                const int nt = pr * 2 + half;
                mma16816(sc[nt], ah, &bh[half * 2]);
                mma16816(sc[nt], ah, &bl[half * 2]);
                mma16816(sc[nt], al, &bh[half * 2]);
            }
        }
    }

    // ---- mask + softmax (rows live in registers of 4-lane groups) ----
    const int er = lane >> 2, ec = (lane & 3) * 2;
    const int qa = w * 16 + er, qb = qa + 8;
    const float SC = 0.125f * 1.44269504088896f;   // scale * log2(e)
    float m0 = -1e30f, m1 = -1e30f;
#pragma unroll
    for (int nt = 0; nt < 24; nt++) {
        int kl = nt * 8 + ec;
        int j  = j0 + kl;
        bool v00 = ((unsigned)(kl     - qa) <= 128u) && ((unsigned)j       < (unsigned)S_LEN);
        bool v01 = ((unsigned)(kl + 1 - qa) <= 128u) && ((unsigned)(j + 1) < (unsigned)S_LEN);
        bool v10 = ((unsigned)(kl     - qb) <= 128u) && ((unsigned)j       < (unsigned)S_LEN);
        bool v11 = ((unsigned)(kl + 1 - qb) <= 128u) && ((unsigned)(j + 1) < (unsigned)S_LEN);
        sc[nt][0] = v00 ? sc[nt][0] * SC : -1e30f;
        sc[nt][1] = v01 ? sc[nt][1] * SC : -1e30f;
        sc[nt][2] = v10 ? sc[nt][2] * SC : -1e30f;
        sc[nt][3] = v11 ? sc[nt][3] * SC : -1e30f;
        m0 = fmaxf(m0, fmaxf(sc[nt][0], sc[nt][1]));
        m1 = fmaxf(m1, fmaxf(sc[nt][2], sc[nt][3]));
    }
    m0 = fmaxf(m0, __shfl_xor_sync(0xffffffffu, m0, 1));
    m0 = fmaxf(m0, __shfl_xor_sync(0xffffffffu, m0, 2));
    m1 = fmaxf(m1, __shfl_xor_sync(0xffffffffu, m1, 1));
    m1 = fmaxf(m1, __shfl_xor_sync(0xffffffffu, m1, 2));

    float s0 = 0.f, s1 = 0.f;
#pragma unroll
    for (int nt = 0; nt < 24; nt++) {
        sc[nt][0] = ex2(sc[nt][0] - m0);
        sc[nt][1] = ex2(sc[nt][1] - m0);
        sc[nt][2] = ex2(sc[nt][2] - m1);
        sc[nt][3] = ex2(sc[nt][3] - m1);
        s0 += sc[nt][0] + sc[nt][1];
        s1 += sc[nt][2] + sc[nt][3];
    }
    s0 += __shfl_xor_sync(0xffffffffu, s0, 1);
    s0 += __shfl_xor_sync(0xffffffffu, s0, 2);
    s1 += __shfl_xor_sync(0xffffffffu, s1, 1);
    s1 += __shfl_xor_sync(0xffffffffu, s1, 2);
    const float inv0 = rcp(s0), inv1 = rcp(s1);

    // ---- O = P V  (P hi/lo x V hi/lo, drop Pl*Vl) ----
    float oa[8][4];
#pragma unroll
    for (int nt = 0; nt < 8; nt++)
#pragma unroll
        for (int r = 0; r < 4; r++) oa[nt][r] = 0.f;

#pragma unroll
    for (int kc = 0; kc < 12; kc++) {
        unsigned ph[4], pl[4];
        ph[0] = packbf(sc[2 * kc][0],     sc[2 * kc][1]);
        ph[1] = packbf(sc[2 * kc][2],     sc[2 * kc][3]);
        ph[2] = packbf(sc[2 * kc + 1][0], sc[2 * kc + 1][1]);
        ph[3] = packbf(sc[2 * kc + 1][2], sc[2 * kc + 1][3]);
        pl[0] = packbf(sc[2 * kc][0]     - bflo_f(ph[0]), sc[2 * kc][1]     - bfhi_f(ph[0]));
        pl[1] = packbf(sc[2 * kc][2]     - bflo_f(ph[1]), sc[2 * kc][3]     - bfhi_f(ph[1]));
        pl[2] = packbf(sc[2 * kc + 1][0] - bflo_f(ph[2]), sc[2 * kc + 1][1] - bfhi_f(ph[2]));
        pl[3] = packbf(sc[2 * kc + 1][2] - bflo_f(ph[3]), sc[2 * kc + 1][3] - bfhi_f(ph[3]));
#pragma unroll
        for (int dt = 0; dt < 4; dt++) {
            unsigned vh[4], vl[4];
            unsigned voff = (unsigned)((kc * 16 + (lane & 15)) * AROWB) + dt * 32 + ((lane >> 4) << 4);
            ldm_x4t(vh, sb + A_SVH + voff);
            ldm_x4t(vl, sb + A_SVL + voff);
            mma16816(oa[2 * dt],     ph, &vh[0]);
            mma16816(oa[2 * dt],     ph, &vl[0]);
            mma16816(oa[2 * dt],     pl, &vh[0]);
            mma16816(oa[2 * dt + 1], ph, &vh[2]);
            mma16816(oa[2 * dt + 1], ph, &vl[2]);
            mma16816(oa[2 * dt + 1], pl, &vh[2]);
        }
    }

    // ---- normalize + write ctx as bf16 hi/lo ----
    const int row0 = q0 + w * 16 + er;
#pragma unroll
    for (int nt = 0; nt < 8; nt++) {
        const int oc = col + nt * 8 + ec;
        float v0 = oa[nt][0] * inv0, v1 = oa[nt][1] * inv0;
        float v2 = oa[nt][2] * inv1, v3 = oa[nt][3] * inv1;
        unsigned hp0 = packbf(v0, v1);
        unsigned lp0 = packbf(v0 - bflo_f(hp0), v1 - bfhi_f(hp0));
        unsigned hp1 = packbf(v2, v3);
        unsigned lp1 = packbf(v2 - bflo_f(hp1), v3 - bfhi_f(hp1));
        *(unsigned*)&g_ch[(size_t)row0 * DMODEL + oc] = hp0;
        *(unsigned*)&g_cl[(size_t)row0 * DMODEL + oc] = lp0;
        *(unsigned*)&g_ch[(size_t)(row0 + 8) * DMODEL + oc] = hp1;
        *(unsigned*)&g_cl[(size_t)(row0 + 8) * DMODEL + oc] = lp1;
    }
}

// ---------------- launch ----------------
extern "C" void kernel_launch(void* const* d_in, const int* in_sizes, int n_in,
                              void* d_out, int out_size)
{
    const float* x  = (const float*)d_in[0];
    const float* Wq = (const float*)d_in[1];
    const float* bq = (const float*)d_in[2];
    const float* Wk = (const float*)d_in[3];
    const float* bk = (const float*)d_in[4];
    const float* Wv = (const float*)d_in[5];
    const float* bv = (const float*)d_in[6];
    const float* Wo = (const float*)d_in[7];
    const float* bo = (const float*)d_in[8];
    float* out = (float*)d_out;

    __nv_bfloat16 *xh, *xl;
    __nv_bfloat16 *wqh, *wql, *wkh, *wkl, *wvh, *wvl, *woh, *wol;
    cudaGetSymbolAddress((void**)&xh, g_xh);   cudaGetSymbolAddress((void**)&xl, g_xl);
    cudaGetSymbolAddress((void**)&wqh, g_Wqh); cudaGetSymbolAddress((void**)&wql, g_Wql);
    cudaGetSymbolAddress((void**)&wkh, g_Wkh); cudaGetSymbolAddress((void**)&wkl, g_Wkl);
    cudaGetSymbolAddress((void**)&wvh, g_Wvh); cudaGetSymbolAddress((void**)&wvl, g_Wvl);
    cudaGetSymbolAddress((void**)&woh, g_Woh); cudaGetSymbolAddress((void**)&wol, g_Wol);

    cudaFuncSetAttribute(gemm_qkv, cudaFuncAttributeMaxDynamicSharedMemorySize, GSMEM);
    cudaFuncSetAttribute(gemm_out, cudaFuncAttributeMaxDynamicSharedMemorySize, GSMEM);
    cudaFuncSetAttribute(attn_mma, cudaFuncAttributeMaxDynamicSharedMemorySize, A_SMEM);

    const int nx = S_LEN * DMODEL;
    const int nw = DMODEL * DMODEL;

    split_bf16<<<nx / 1024, 256>>>(x,  xh,  xl);
    split_bf16<<<nw / 1024, 256>>>(Wq, wqh, wql);
    split_bf16<<<nw / 1024, 256>>>(Wk, wkh, wkl);
    split_bf16<<<nw / 1024, 256>>>(Wv, wvh, wvl);
    split_bf16<<<nw / 1024, 256>>>(Wo, woh, wol);

    dim3 gq(24, 32);                       // fused Q,K,V
    gemm_qkv<<<gq, 256, GSMEM>>>(bq, bk, bv);

    dim3 ga(S_LEN / AT_Q, N_HEADS);        // (64, 16)
    attn_mma<<<ga, 128, A_SMEM>>>();

    dim3 go(8, 32);
    gemm_out<<<go, 256, GSMEM>>>(bo, out);
}

// round 6
// speedup vs baseline: 2.3766x; 1.1478x over previous
#include <cuda_runtime.h>
#include <cuda_bf16.h>
#include <math.h>

// ---------------- problem constants ----------------
#define S_LEN    4096
#define DMODEL   1024
#define N_HEADS  16
#define HEAD_DIM 64

// ---------------- scratch (no allocations allowed) ----------------
__device__ __nv_bfloat16 g_xh[S_LEN * DMODEL];
__device__ __nv_bfloat16 g_xl[S_LEN * DMODEL];
__device__ __nv_bfloat16 g_qh[S_LEN * DMODEL];
__device__ __nv_bfloat16 g_ql[S_LEN * DMODEL];
__device__ __nv_bfloat16 g_kh[S_LEN * DMODEL];
__device__ __nv_bfloat16 g_kl[S_LEN * DMODEL];
__device__ __nv_bfloat16 g_vh[S_LEN * DMODEL];
__device__ __nv_bfloat16 g_vl[S_LEN * DMODEL];
__device__ __nv_bfloat16 g_ch[S_LEN * DMODEL];
__device__ __nv_bfloat16 g_cl[S_LEN * DMODEL];
__device__ __nv_bfloat16 g_Wqh[DMODEL * DMODEL];
__device__ __nv_bfloat16 g_Wql[DMODEL * DMODEL];
__device__ __nv_bfloat16 g_Wkh[DMODEL * DMODEL];
__device__ __nv_bfloat16 g_Wkl[DMODEL * DMODEL];
__device__ __nv_bfloat16 g_Wvh[DMODEL * DMODEL];
__device__ __nv_bfloat16 g_Wvl[DMODEL * DMODEL];
__device__ __nv_bfloat16 g_Woh[DMODEL * DMODEL];
__device__ __nv_bfloat16 g_Wol[DMODEL * DMODEL];

// ---------------- small helpers ----------------
__device__ __forceinline__ unsigned smem_u32(const void* p) {
    unsigned a;
    asm("{ .reg .u64 t; cvta.to.shared.u64 t, %1; cvt.u32.u64 %0, t; }" : "=r"(a) : "l"(p));
    return a;
}
__device__ __forceinline__ void cp16(unsigned dst, const void* src) {
    asm volatile("cp.async.cg.shared.global [%0], [%1], 16;" :: "r"(dst), "l"(src));
}
__device__ __forceinline__ void ldm_x4(unsigned* r, unsigned addr) {
    asm volatile("ldmatrix.sync.aligned.m8n8.x4.shared.b16 {%0,%1,%2,%3}, [%4];"
                 : "=r"(r[0]), "=r"(r[1]), "=r"(r[2]), "=r"(r[3]) : "r"(addr));
}
__device__ __forceinline__ void ldm_x4t(unsigned* r, unsigned addr) {
    asm volatile("ldmatrix.sync.aligned.m8n8.x4.trans.shared.b16 {%0,%1,%2,%3}, [%4];"
                 : "=r"(r[0]), "=r"(r[1]), "=r"(r[2]), "=r"(r[3]) : "r"(addr));
}
__device__ __forceinline__ void mma16816(float* d, const unsigned* a, const unsigned* b) {
    asm volatile(
        "mma.sync.aligned.m16n8k16.row.col.f32.bf16.bf16.f32 "
        "{%0,%1,%2,%3}, {%4,%5,%6,%7}, {%8,%9}, {%0,%1,%2,%3};"
        : "+f"(d[0]), "+f"(d[1]), "+f"(d[2]), "+f"(d[3])
        : "r"(a[0]), "r"(a[1]), "r"(a[2]), "r"(a[3]), "r"(b[0]), "r"(b[1]));
}
__device__ __forceinline__ unsigned packbf(float lo, float hi) {
    unsigned r;
    asm("cvt.rn.bf16x2.f32 %0, %1, %2;" : "=r"(r) : "f"(hi), "f"(lo));
    return r;
}
__device__ __forceinline__ float bflo_f(unsigned u) { return __uint_as_float(u << 16); }
__device__ __forceinline__ float bfhi_f(unsigned u) { return __uint_as_float(u & 0xffff0000u); }
__device__ __forceinline__ float ex2(float x) {
    float y; asm("ex2.approx.ftz.f32 %0, %1;" : "=f"(y) : "f"(x)); return y;
}
__device__ __forceinline__ float rcp(float x) {
    float y; asm("rcp.approx.ftz.f32 %0, %1;" : "=f"(y) : "f"(x)); return y;
}

// ---------------- split: fp32 -> bf16 hi + bf16 lo ----------------
__global__ __launch_bounds__(256)
void split_bf16(const float* __restrict__ in, __nv_bfloat16* __restrict__ hi,
                __nv_bfloat16* __restrict__ lo)
{
    int i = (blockIdx.x * 256 + threadIdx.x) * 4;
    float4 a = *(const float4*)(in + i);
    unsigned h0 = packbf(a.x, a.y), h1 = packbf(a.z, a.w);
    unsigned l0 = packbf(a.x - bflo_f(h0), a.y - bfhi_f(h0));
    unsigned l1 = packbf(a.z - bflo_f(h1), a.w - bfhi_f(h1));
    uint2 hp = make_uint2(h0, h1), lp = make_uint2(l0, l1);
    *(uint2*)((__nv_bfloat16*)hi + i) = hp;
    *(uint2*)((__nv_bfloat16*)lo + i) = lp;
}

// ---------------- shared GEMM body (mma.sync bf16x3) ----------------
// 128x128 tile, BK=32, 8 warps (2x4), warp tile 64x32.
// 2-stage cp.async, 2 CTAs/SM for bubble overlap.
#define ROWB   80
#define PLANE  (128 * ROWB)
#define STAGE  (4 * PLANE)
#define NSTAGE 2
#define GSMEM  (NSTAGE * STAGE)          // 81920 B -> 2 CTAs/SM
#define NCHUNK 32

// mode 0: C = fp32 out+bias ; mode 1: write bf16 hi/lo pair arrays
__device__ __forceinline__
void gemm_body(char* smem,
               const __nv_bfloat16* __restrict__ Ah, const __nv_bfloat16* __restrict__ Al,
               const __nv_bfloat16* __restrict__ Bh, const __nv_bfloat16* __restrict__ Bl,
               const float* __restrict__ bias, int bm, int bn,
               int mode, float* __restrict__ C,
               __nv_bfloat16* __restrict__ Ch, __nv_bfloat16* __restrict__ Cl)
{
    const int t = threadIdx.x, lane = t & 31, wid = t >> 5;
    const int wm = wid >> 2, wn = wid & 3;

    float acc[4][4][4];
#pragma unroll
    for (int mt = 0; mt < 4; mt++)
#pragma unroll
        for (int nt = 0; nt < 4; nt++)
#pragma unroll
            for (int r = 0; r < 4; r++) acc[mt][nt][r] = 0.f;

    const int r0 = t >> 2, s0 = t & 3;
    const int r1 = r0 + 64;

    const __nv_bfloat16* srcs[4] = {Ah, Al, Bh, Bl};
    const int rowbase[4] = {bm, bm, bn, bn};

#define ISSUE(cc)                                                                 \
    {                                                                             \
        char* sb = smem + ((cc) & (NSTAGE - 1)) * STAGE;                          \
        const int gk = (cc) * 32 + s0 * 8;                                        \
        _Pragma("unroll")                                                         \
        for (int pl = 0; pl < 4; pl++) {                                          \
            const __nv_bfloat16* gp = srcs[pl] + (size_t)rowbase[pl] * DMODEL + gk; \
            unsigned db = smem_u32(sb + pl * PLANE + s0 * 16);                    \
            cp16(db + r0 * ROWB, gp + (size_t)r0 * DMODEL);                       \
            cp16(db + r1 * ROWB, gp + (size_t)r1 * DMODEL);                       \
        }                                                                         \
        asm volatile("cp.async.commit_group;" ::: "memory");                      \
    }

    ISSUE(0); ISSUE(1);

    const int a_row = wm * 64 + (lane & 15);
    const unsigned a_coff = (lane >> 4) * 16;
    const int b_row = wn * 32 + (lane & 7) + ((lane >> 4) << 3);
    const unsigned b_coff = ((lane >> 3) & 1) * 16;

    for (int c = 0; c < NCHUNK; c++) {
        if (c + 1 < NCHUNK) {
            asm volatile("cp.async.wait_group 1;" ::: "memory");
        } else {
            asm volatile("cp.async.wait_group 0;" ::: "memory");
        }
        __syncthreads();

        char* sb = smem + (c & (NSTAGE - 1)) * STAGE;
        const unsigned sAh = smem_u32(sb);
        const unsigned sAl = sAh + PLANE;
        const unsigned sBh = sAh + 2 * PLANE;
        const unsigned sBl = sAh + 3 * PLANE;

#pragma unroll
        for (int ks = 0; ks < 2; ks++) {
            const unsigned ka = ks * 32;
            unsigned ah[4][4], al[4][4];
#pragma unroll
            for (int mt = 0; mt < 4; mt++) {
                unsigned off = (unsigned)((a_row + mt * 16) * ROWB) + ka + a_coff;
                ldm_x4(ah[mt], sAh + off);
                ldm_x4(al[mt], sAl + off);
            }
#pragma unroll
            for (int pr = 0; pr < 2; pr++) {
                unsigned bh[4], bl[4];
                unsigned off = (unsigned)((b_row + pr * 16) * ROWB) + ka + b_coff;
                ldm_x4(bh, sBh + off);
                ldm_x4(bl, sBl + off);
#pragma unroll
                for (int half = 0; half < 2; half++) {
                    const int nt = pr * 2 + half;
#pragma unroll
                    for (int mt = 0; mt < 4; mt++) {
                        mma16816(acc[mt][nt], ah[mt], &bh[half * 2]);
                        mma16816(acc[mt][nt], ah[mt], &bl[half * 2]);
                        mma16816(acc[mt][nt], al[mt], &bh[half * 2]);
                    }
                }
            }
        }
        __syncthreads();
        if (c + 2 < NCHUNK) ISSUE(c + 2);
    }
#undef ISSUE

    // ---- epilogue ----
    const int er = lane >> 2, ec = (lane & 3) * 2;
#pragma unroll
    for (int mt = 0; mt < 4; mt++) {
        const int row = bm + wm * 64 + mt * 16 + er;
#pragma unroll
        for (int nt = 0; nt < 4; nt++) {
            const int col = bn + wn * 32 + nt * 8 + ec;
            const float b0 = bias[col], b1 = bias[col + 1];
            float v0 = acc[mt][nt][0] + b0, v1 = acc[mt][nt][1] + b1;
            float v2 = acc[mt][nt][2] + b0, v3 = acc[mt][nt][3] + b1;
            if (mode == 0) {
                *(float2*)&C[(size_t)row * DMODEL + col] = make_float2(v0, v1);
                *(float2*)&C[(size_t)(row + 8) * DMODEL + col] = make_float2(v2, v3);
            } else {
                unsigned hp0 = packbf(v0, v1);
                unsigned lp0 = packbf(v0 - bflo_f(hp0), v1 - bfhi_f(hp0));
                unsigned hp1 = packbf(v2, v3);
                unsigned lp1 = packbf(v2 - bflo_f(hp1), v3 - bfhi_f(hp1));
                *(unsigned*)&Ch[(size_t)row * DMODEL + col] = hp0;
                *(unsigned*)&Cl[(size_t)row * DMODEL + col] = lp0;
                *(unsigned*)&Ch[(size_t)(row + 8) * DMODEL + col] = hp1;
                *(unsigned*)&Cl[(size_t)(row + 8) * DMODEL + col] = lp1;
            }
        }
    }
}

// ---- fused QKV projection: grid (24, 32); blockIdx.x/8 selects Q/K/V ----
__global__ __launch_bounds__(256, 2)
void gemm_qkv(const float* __restrict__ bq, const float* __restrict__ bk,
              const float* __restrict__ bv)
{
    extern __shared__ char smem[];
    const int which = blockIdx.x >> 3;
    const int bn = (blockIdx.x & 7) * 128;
    const int bm = blockIdx.y * 128;
    const __nv_bfloat16* Bh = (which == 0) ? g_Wqh : (which == 1) ? g_Wkh : g_Wvh;
    const __nv_bfloat16* Bl = (which == 0) ? g_Wql : (which == 1) ? g_Wkl : g_Wvl;
    const float* bias = (which == 0) ? bq : (which == 1) ? bk : bv;
    __nv_bfloat16* Ch = (which == 0) ? g_qh : (which == 1) ? g_kh : g_vh;
    __nv_bfloat16* Cl = (which == 0) ? g_ql : (which == 1) ? g_kl : g_vl;
    gemm_body(smem, g_xh, g_xl, Bh, Bl, bias, bm, bn, 1, nullptr, Ch, Cl);
}

// ---- output projection: ctx(hi/lo) @ Wo^T + bo -> fp32 out ----
__global__ __launch_bounds__(256, 2)
void gemm_out(const float* __restrict__ bo, float* __restrict__ out)
{
    extern __shared__ char smem[];
    gemm_body(smem, g_ch, g_cl, g_Woh, g_Wol, bo,
              blockIdx.y * 128, blockIdx.x * 128, 0, out, nullptr, nullptr);
}

// ---------------- tensorized sliding-window attention ----------------
// grid (S/64, H), 128 threads (4 warps). Each warp: 16 query rows x 192 keys.
#define AT_Q   64
#define AT_K   192
#define AROWB  144
#define A_SQH  0
#define A_SQL  (64 * AROWB)
#define A_SKH  (2 * 64 * AROWB)
#define A_SKL  (A_SKH + AT_K * AROWB)
#define A_SVH  (A_SKL + AT_K * AROWB)
#define A_SVL  (A_SVH + AT_K * AROWB)
#define A_SMEM (A_SVL + AT_K * AROWB)       // 129024

__global__ __launch_bounds__(128)
void attn_mma()
{
    extern __shared__ char smem[];
    const unsigned sb = smem_u32(smem);
    const int t = threadIdx.x, lane = t & 31, w = t >> 5;
    const int h = blockIdx.y;
    const int q0 = blockIdx.x * AT_Q;
    const int j0 = q0 - 64;
    const int col = h * HEAD_DIM;

#pragma unroll
    for (int i = 0; i < 4; i++) {
        int idx = t + i * 128;
        int r = idx >> 3, sg = idx & 7;
        size_t go = (size_t)(q0 + r) * DMODEL + col + sg * 8;
        *(uint4*)(smem + A_SQH + r * AROWB + sg * 16) = *(const uint4*)(g_qh + go);
        *(uint4*)(smem + A_SQL + r * AROWB + sg * 16) = *(const uint4*)(g_ql + go);
    }
#pragma unroll
    for (int i = 0; i < 12; i++) {
        int idx = t + i * 128;
        int r = idx >> 3, sg = idx & 7;
        int j = j0 + r;
        uint4 kh = make_uint4(0,0,0,0), kl = kh, vh = kh, vl = kh;
        if ((unsigned)j < (unsigned)S_LEN) {
            size_t go = (size_t)j * DMODEL + col + sg * 8;
            kh = *(const uint4*)(g_kh + go);
            kl = *(const uint4*)(g_kl + go);
            vh = *(const uint4*)(g_vh + go);
            vl = *(const uint4*)(g_vl + go);
        }
        unsigned so = r * AROWB + sg * 16;
        *(uint4*)(smem + A_SKH + so) = kh;
        *(uint4*)(smem + A_SKL + so) = kl;
        *(uint4*)(smem + A_SVH + so) = vh;
        *(uint4*)(smem + A_SVL + so) = vl;
    }
    __syncthreads();

    float sc[24][4];
#pragma unroll
    for (int nt = 0; nt < 24; nt++)
#pragma unroll
        for (int r = 0; r < 4; r++) sc[nt][r] = 0.f;

    const unsigned a_base = (unsigned)((w * 16 + (lane & 15)) * AROWB) + ((lane >> 4) << 4);
    const int b_lrow = (lane & 7) + ((lane >> 4) << 3);
    const unsigned b_coff = ((lane >> 3) & 1) << 4;

#pragma unroll
    for (int kc = 0; kc < 4; kc++) {
        unsigned ah[4], al[4];
        ldm_x4(ah, sb + A_SQH + a_base + kc * 32);
        ldm_x4(al, sb + A_SQL + a_base + kc * 32);
#pragma unroll
        for (int pr = 0; pr < 12; pr++) {
            unsigned bh[4], bl[4];
            unsigned off = (unsigned)((pr * 16 + b_lrow) * AROWB) + kc * 32 + b_coff;
            ldm_x4(bh, sb + A_SKH + off);
            ldm_x4(bl, sb + A_SKL + off);
#pragma unroll
            for (int half = 0; half < 2; half++) {
                const int nt = pr * 2 + half;
                mma16816(sc[nt], ah, &bh[half * 2]);
                mma16816(sc[nt], ah, &bl[half * 2]);
                mma16816(sc[nt], al, &bh[half * 2]);
            }
        }
    }

    const int er = lane >> 2, ec = (lane & 3) * 2;
    const int qa = w * 16 + er, qb = qa + 8;
    const float SC = 0.125f * 1.44269504088896f;
    float m0 = -1e30f, m1 = -1e30f;
#pragma unroll
    for (int nt = 0; nt < 24; nt++) {
        int kl = nt * 8 + ec;
        int j  = j0 + kl;
        bool v00 = ((unsigned)(kl     - qa) <= 128u) && ((unsigned)j       < (unsigned)S_LEN);
        bool v01 = ((unsigned)(kl + 1 - qa) <= 128u) && ((unsigned)(j + 1) < (unsigned)S_LEN);
        bool v10 = ((unsigned)(kl     - qb) <= 128u) && ((unsigned)j       < (unsigned)S_LEN);
        bool v11 = ((unsigned)(kl + 1 - qb) <= 128u) && ((unsigned)(j + 1) < (unsigned)S_LEN);
        sc[nt][0] = v00 ? sc[nt][0] * SC : -1e30f;
        sc[nt][1] = v01 ? sc[nt][1] * SC : -1e30f;
        sc[nt][2] = v10 ? sc[nt][2] * SC : -1e30f;
        sc[nt][3] = v11 ? sc[nt][3] * SC : -1e30f;
        m0 = fmaxf(m0, fmaxf(sc[nt][0], sc[nt][1]));
        m1 = fmaxf(m1, fmaxf(sc[nt][2], sc[nt][3]));
    }
    m0 = fmaxf(m0, __shfl_xor_sync(0xffffffffu, m0, 1));
    m0 = fmaxf(m0, __shfl_xor_sync(0xffffffffu, m0, 2));
    m1 = fmaxf(m1, __shfl_xor_sync(0xffffffffu, m1, 1));
    m1 = fmaxf(m1, __shfl_xor_sync(0xffffffffu, m1, 2));

    float s0 = 0.f, s1 = 0.f;
#pragma unroll
    for (int nt = 0; nt < 24; nt++) {
        sc[nt][0] = ex2(sc[nt][0] - m0);
        sc[nt][1] = ex2(sc[nt][1] - m0);
        sc[nt][2] = ex2(sc[nt][2] - m1);
        sc[nt][3] = ex2(sc[nt][3] - m1);
        s0 += sc[nt][0] + sc[nt][1];
        s1 += sc[nt][2] + sc[nt][3];
    }
    s0 += __shfl_xor_sync(0xffffffffu, s0, 1);
    s0 += __shfl_xor_sync(0xffffffffu, s0, 2);
    s1 += __shfl_xor_sync(0xffffffffu, s1, 1);
    s1 += __shfl_xor_sync(0xffffffffu, s1, 2);
    const float inv0 = rcp(s0), inv1 = rcp(s1);

    float oa[8][4];
#pragma unroll
    for (int nt = 0; nt < 8; nt++)
#pragma unroll
        for (int r = 0; r < 4; r++) oa[nt][r] = 0.f;

#pragma unroll
    for (int kc = 0; kc < 12; kc++) {
        unsigned ph[4], pl[4];
        ph[0] = packbf(sc[2 * kc][0],     sc[2 * kc][1]);
        ph[1] = packbf(sc[2 * kc][2],     sc[2 * kc][3]);
        ph[2] = packbf(sc[2 * kc + 1][0], sc[2 * kc + 1][1]);
        ph[3] = packbf(sc[2 * kc + 1][2], sc[2 * kc + 1][3]);
        pl[0] = packbf(sc[2 * kc][0]     - bflo_f(ph[0]), sc[2 * kc][1]     - bfhi_f(ph[0]));
        pl[1] = packbf(sc[2 * kc][2]     - bflo_f(ph[1]), sc[2 * kc][3]     - bfhi_f(ph[1]));
        pl[2] = packbf(sc[2 * kc + 1][0] - bflo_f(ph[2]), sc[2 * kc + 1][1] - bfhi_f(ph[2]));
        pl[3] = packbf(sc[2 * kc + 1][2] - bflo_f(ph[3]), sc[2 * kc + 1][3] - bfhi_f(ph[3]));
#pragma unroll
        for (int dt = 0; dt < 4; dt++) {
            unsigned vh[4], vl[4];
            unsigned voff = (unsigned)((kc * 16 + (lane & 15)) * AROWB) + dt * 32 + ((lane >> 4) << 4);
            ldm_x4t(vh, sb + A_SVH + voff);
            ldm_x4t(vl, sb + A_SVL + voff);
            mma16816(oa[2 * dt],     ph, &vh[0]);
            mma16816(oa[2 * dt],     ph, &vl[0]);
            mma16816(oa[2 * dt],     pl, &vh[0]);
            mma16816(oa[2 * dt + 1], ph, &vh[2]);
            mma16816(oa[2 * dt + 1], ph, &vl[2]);
            mma16816(oa[2 * dt + 1], pl, &vh[2]);
        }
    }

    const int row0 = q0 + w * 16 + er;
#pragma unroll
    for (int nt = 0; nt < 8; nt++) {
        const int oc = col + nt * 8 + ec;
        float v0 = oa[nt][0] * inv0, v1 = oa[nt][1] * inv0;
        float v2 = oa[nt][2] * inv1, v3 = oa[nt][3] * inv1;
        unsigned hp0 = packbf(v0, v1);
        unsigned lp0 = packbf(v0 - bflo_f(hp0), v1 - bfhi_f(hp0));
        unsigned hp1 = packbf(v2, v3);
        unsigned lp1 = packbf(v2 - bflo_f(hp1), v3 - bfhi_f(hp1));
        *(unsigned*)&g_ch[(size_t)row0 * DMODEL + oc] = hp0;
        *(unsigned*)&g_cl[(size_t)row0 * DMODEL + oc] = lp0;
        *(unsigned*)&g_ch[(size_t)(row0 + 8) * DMODEL + oc] = hp1;
        *(unsigned*)&g_cl[(size_t)(row0 + 8) * DMODEL + oc] = lp1;
    }
}

// ---------------- launch ----------------
extern "C" void kernel_launch(void* const* d_in, const int* in_sizes, int n_in,
                              void* d_out, int out_size)
{
    const float* x  = (const float*)d_in[0];
    const float* Wq = (const float*)d_in[1];
    const float* bq = (const float*)d_in[2];
    const float* Wk = (const float*)d_in[3];
    const float* bk = (const float*)d_in[4];
    const float* Wv = (const float*)d_in[5];
    const float* bv = (const float*)d_in[6];
    const float* Wo = (const float*)d_in[7];
    const float* bo = (const float*)d_in[8];
    float* out = (float*)d_out;

    __nv_bfloat16 *xh, *xl;
    __nv_bfloat16 *wqh, *wql, *wkh, *wkl, *wvh, *wvl, *woh, *wol;
    cudaGetSymbolAddress((void**)&xh, g_xh);   cudaGetSymbolAddress((void**)&xl, g_xl);
    cudaGetSymbolAddress((void**)&wqh, g_Wqh); cudaGetSymbolAddress((void**)&wql, g_Wql);
    cudaGetSymbolAddress((void**)&wkh, g_Wkh); cudaGetSymbolAddress((void**)&wkl, g_Wkl);
    cudaGetSymbolAddress((void**)&wvh, g_Wvh); cudaGetSymbolAddress((void**)&wvl, g_Wvl);
    cudaGetSymbolAddress((void**)&woh, g_Woh); cudaGetSymbolAddress((void**)&wol, g_Wol);

    cudaFuncSetAttribute(gemm_qkv, cudaFuncAttributeMaxDynamicSharedMemorySize, GSMEM);
    cudaFuncSetAttribute(gemm_out, cudaFuncAttributeMaxDynamicSharedMemorySize, GSMEM);
    cudaFuncSetAttribute(attn_mma, cudaFuncAttributeMaxDynamicSharedMemorySize, A_SMEM);

    const int nx = S_LEN * DMODEL;
    const int nw = DMODEL * DMODEL;

    split_bf16<<<nx / 1024, 256>>>(x,  xh,  xl);
    split_bf16<<<nw / 1024, 256>>>(Wq, wqh, wql);
    split_bf16<<<nw / 1024, 256>>>(Wk, wkh, wkl);
    split_bf16<<<nw / 1024, 256>>>(Wv, wvh, wvl);
    split_bf16<<<nw / 1024, 256>>>(Wo, woh, wol);

    dim3 gq(24, 32);                       // fused Q,K,V
    gemm_qkv<<<gq, 256, GSMEM>>>(bq, bk, bv);

    dim3 ga(S_LEN / AT_Q, N_HEADS);        // (64, 16)
    attn_mma<<<ga, 128, A_SMEM>>>();

    dim3 go(8, 32);
    gemm_out<<<go, 256, GSMEM>>>(bo, out);
}